// round 7
// baseline (speedup 1.0000x reference)
#include <cuda_runtime.h>
#include <cuda_fp16.h>
#include <stdint.h>

// ---------------- problem constants -----------------------------------------
#define LL 4096
#define BB 4
#define DD 1024
#define HH 16
#define HD 64
#define ROWS (LL*BB)          // 16384
#define BH   (BB*HH)          // 64
#define KV_PARTS 8
#define LPART (LL/KV_PARTS)   // 512

// ---------------- scratch (device globals; cudaMalloc is banned) ------------
__device__ __align__(256) __half g_xh  [(size_t)ROWS*DD];    // X in f16
__device__ __align__(256) __half g_wh  [(size_t)3*DD*DD];    // [Wq;Wk;Wv] f16
__device__ __align__(256) __half g_woph[(size_t)DD*DD];      // Wo permuted f16
__device__ __align__(256) float  g_bqkv[(size_t)3*DD];       // [bq;bk;bv]
__device__ __align__(256) __half g_qh  [(size_t)ROWS*DD];    // q (unscaled) f16
__device__ __align__(256) __half g_kh  [(size_t)ROWS*DD];
__device__ __align__(256) __half g_vh  [(size_t)ROWS*DD];
__device__ __align__(256) __half g_ah  [(size_t)ROWS*DD];    // attn out f16
__device__ __align__(256) float  g_kvp [(size_t)KV_PARTS*BH*HD*HD];
__device__ __align__(256) float  g_kvT [(size_t)BH*HD*HD];

// ---------------- helpers -----------------------------------------------------
__device__ __forceinline__ uint32_t f2tf(float x) {
    uint32_t u; asm("cvt.rna.tf32.f32 %0, %1;" : "=r"(u) : "f"(x)); return u;
}
__device__ __forceinline__ uint32_t smem_u32(const void* p) {
    uint32_t a;
    asm("{ .reg .u64 t; cvta.to.shared.u64 t, %1; cvt.u32.u64 %0, t; }" : "=r"(a) : "l"(p));
    return a;
}
__device__ __forceinline__ void cp16(uint32_t saddr, const void* gaddr) {
    asm volatile("cp.async.cg.shared.global [%0], [%1], 16;" :: "r"(saddr), "l"(gaddr));
}
__device__ __forceinline__ void ldsm4(uint32_t* r, uint32_t a) {
    asm volatile("ldmatrix.sync.aligned.m8n8.x4.shared.b16 {%0,%1,%2,%3}, [%4];"
        : "=r"(r[0]), "=r"(r[1]), "=r"(r[2]), "=r"(r[3]) : "r"(a));
}
__device__ __forceinline__ void mma16(float c[4], const uint32_t a[4],
                                      uint32_t b0, uint32_t b1) {
    asm volatile(
        "mma.sync.aligned.m16n8k16.row.col.f32.f16.f16.f32 "
        "{%0,%1,%2,%3}, {%4,%5,%6,%7}, {%8,%9}, {%0,%1,%2,%3};"
        : "+f"(c[0]), "+f"(c[1]), "+f"(c[2]), "+f"(c[3])
        : "r"(a[0]), "r"(a[1]), "r"(a[2]), "r"(a[3]), "r"(b0), "r"(b1));
}
__device__ __forceinline__ void mma8(float c[4], const uint32_t a[4],
                                     uint32_t b0, uint32_t b1) {
    asm volatile(
        "mma.sync.aligned.m16n8k8.row.col.f32.tf32.tf32.f32 "
        "{%0,%1,%2,%3}, {%4,%5,%6,%7}, {%8,%9}, {%0,%1,%2,%3};"
        : "+f"(c[0]), "+f"(c[1]), "+f"(c[2]), "+f"(c[3])
        : "r"(a[0]), "r"(a[1]), "r"(a[2]), "r"(a[3]), "r"(b0), "r"(b1));
}

// =============================================================================
// Prep kernels
// =============================================================================
__global__ void x_to_h(const float* __restrict__ X) {
    size_t i = ((size_t)blockIdx.x * 256 + threadIdx.x) * 4;
    float4 v = *(const float4*)(X + i);
    *(__half2*)(g_xh + i)     = __floats2half2_rn(v.x, v.y);
    *(__half2*)(g_xh + i + 2) = __floats2half2_rn(v.z, v.w);
}

__global__ void pack_wh(const float* __restrict__ Wq, const float* __restrict__ Wk,
                        const float* __restrict__ Wv) {
    int r = blockIdx.x;                                 // 0..3071
    const float* src = (r < 1024) ? Wq : (r < 2048) ? Wk : Wv;
    int lr = r & 1023;
    int c = threadIdx.x * 4;
    float4 v = *(const float4*)(src + (size_t)lr * DD + c);
    *(__half2*)(g_wh + (size_t)r * DD + c)     = __floats2half2_rn(v.x, v.y);
    *(__half2*)(g_wh + (size_t)r * DD + c + 2) = __floats2half2_rn(v.z, v.w);
}

__global__ void pack_b(const float* __restrict__ bq, const float* __restrict__ bk,
                       const float* __restrict__ bv) {
    int t = blockIdx.x;
    const float* src = (t == 0) ? bq : (t == 1) ? bk : bv;
    g_bqkv[t * DD + threadIdx.x] = src[threadIdx.x];
}

// g_woph[j][h*64+t] = half(Wo[j][t*16+h])
__global__ void wo_permute_h(const float* __restrict__ Wo) {
    __shared__ float srow[DD];
    const int j = blockIdx.x, tid = threadIdx.x;
#pragma unroll
    for (int i = 0; i < 4; ++i) srow[tid + 256*i] = Wo[(size_t)j*DD + tid + 256*i];
    __syncthreads();
#pragma unroll
    for (int i = 0; i < 4; ++i) {
        int f = tid + 256*i;
        g_woph[(size_t)j*DD + f] = __float2half_rn(srow[((f & 63) << 4) | (f >> 6)]);
    }
}

// =============================================================================
// FP16 tensor-core GEMM:  C = A @ B^T + bias
//   block 128x128, BK=64, 4 warps, warp tile 64x64, 3-stage cp.async pipeline,
//   ldmatrix.x4, XOR-8 swizzled 128B smem rows, double-buffered fragments,
//   single barrier per K-chunk.  2 CTAs/SM.
// =============================================================================
#define STA  16384                 // A stage bytes (128 rows x 128B)
#define STS_ (2*STA)               // 32768
#define GSMEM (3 * STS_)           // 98304
#define NKT  16                    // 1024 / 64

__global__ void __launch_bounds__(128, 2) gemm_h(
    const __half* __restrict__ A, const __half* __restrict__ B,
    const float* __restrict__ bias,
    void* __restrict__ o0, void* __restrict__ o1, void* __restrict__ o2,
    int half_out)
{
    extern __shared__ char smem[];
    const uint32_t sb = smem_u32(smem);
    const int tid  = threadIdx.x;
    const int wid  = tid >> 5;
    const int lane = tid & 31;
    const int n0 = blockIdx.x * 128;
    const int m0 = blockIdx.y * 128;
    const int wm = (wid & 1) * 64;
    const int wn = (wid >> 1) * 64;

    // staging offsets (128B rows, seg ^= row&7 swizzle); same map for A and B
    uint32_t sm_off[8], g_off[8];
#pragma unroll
    for (int i = 0; i < 8; ++i) {
        int s = tid + 128*i, row = s >> 3, seg = s & 7;
        sm_off[i] = row*128 + ((seg ^ (row & 7)) << 4);
        g_off[i]  = (uint32_t)row*2048 + seg*16;
    }
    const char* Abase = (const char*)A + (size_t)m0 * 2048;
    const char* Bbase = (const char*)B + (size_t)n0 * 2048;

#define LOADC(c) do {                                                   \
        int st_ = (c) % 3;                                              \
        uint32_t ab_ = sb + st_*STS_;                                   \
        uint32_t bb_ = ab_ + STA;                                       \
        const char* ga_ = Abase + (size_t)(c)*128;                      \
        const char* gb_ = Bbase + (size_t)(c)*128;                      \
        _Pragma("unroll") for (int i_ = 0; i_ < 8; ++i_) {              \
            cp16(ab_ + sm_off[i_], ga_ + g_off[i_]);                    \
            cp16(bb_ + sm_off[i_], gb_ + g_off[i_]);                    \
        }                                                               \
        asm volatile("cp.async.commit_group;" ::: "memory");            \
    } while (0)

// load fragments for k16 step (s) of the current stage into buffer (buf)
#define LOADFRAG(buf, s) do {                                           \
        _Pragma("unroll") for (int mt_ = 0; mt_ < 4; ++mt_) {           \
            int r_  = wm + mt_*16 + (lane & 15);                        \
            int sg_ = (2*(s) + (lane >> 4)) ^ (r_ & 7);                 \
            ldsm4(af[buf][mt_], sa + r_*128 + (sg_ << 4));              \
        }                                                               \
        _Pragma("unroll") for (int p_ = 0; p_ < 4; ++p_) {              \
            int r_  = wn + p_*16 + (lane & 7) + ((lane >> 4) << 3);     \
            int sg_ = (2*(s) + ((lane >> 3) & 1)) ^ (r_ & 7);           \
            ldsm4(bf[buf][p_], sbB + r_*128 + (sg_ << 4));              \
        }                                                               \
    } while (0)

    float acc[4][8][4];
#pragma unroll
    for (int i = 0; i < 4; ++i)
#pragma unroll
        for (int j = 0; j < 8; ++j)
#pragma unroll
            for (int t = 0; t < 4; ++t) acc[i][j][t] = 0.f;

    LOADC(0);
    LOADC(1);

    uint32_t af[2][4][4], bf[2][4][4];

    for (int kt = 0; kt < NKT; ++kt) {
        if (kt + 1 < NKT) asm volatile("cp.async.wait_group 1;" ::: "memory");
        else              asm volatile("cp.async.wait_group 0;" ::: "memory");
        __syncthreads();          // single barrier per K-chunk (see pipeline proof)
        if (kt + 2 < NKT) LOADC(kt + 2);

        const uint32_t sa  = sb + (kt % 3) * STS_;
        const uint32_t sbB = sa + STA;

        LOADFRAG(0, 0);
#pragma unroll
        for (int s = 0; s < 4; ++s) {          // four k16 steps within BK=64
            const int cur = s & 1;
            if (s < 3) LOADFRAG(cur ^ 1, s + 1);
#pragma unroll
            for (int mt = 0; mt < 4; ++mt)
#pragma unroll
                for (int nt = 0; nt < 8; ++nt)
                    mma16(acc[mt][nt], af[cur][mt],
                          bf[cur][nt >> 1][(nt & 1) * 2],
                          bf[cur][nt >> 1][(nt & 1) * 2 + 1]);
        }
    }

    // epilogue
    if (half_out) {
        const int t = n0 >> 10;
        __half* outp = (t == 0) ? (__half*)o0 : (t == 1) ? (__half*)o1 : (__half*)o2;
#pragma unroll
        for (int mt = 0; mt < 4; ++mt) {
#pragma unroll
            for (int nt = 0; nt < 8; ++nt) {
                int row = m0 + wm + mt*16 + (lane >> 2);
                int gn  = n0 + wn + nt*8 + 2*(lane & 3);
                int col = gn & 1023;
                float b0 = bias[gn], b1 = bias[gn + 1];
                *(__half2*)&outp[(size_t)row * 1024 + col] =
                    __floats2half2_rn(acc[mt][nt][0] + b0, acc[mt][nt][1] + b1);
                *(__half2*)&outp[(size_t)(row + 8) * 1024 + col] =
                    __floats2half2_rn(acc[mt][nt][2] + b0, acc[mt][nt][3] + b1);
            }
        }
    } else {
        float* outp = (float*)o0;
#pragma unroll
        for (int mt = 0; mt < 4; ++mt) {
#pragma unroll
            for (int nt = 0; nt < 8; ++nt) {
                int row = m0 + wm + mt*16 + (lane >> 2);
                int gn  = n0 + wn + nt*8 + 2*(lane & 3);
                float b0 = bias[gn], b1 = bias[gn + 1];
                *(float2*)&outp[(size_t)row * 1024 + gn] =
                    make_float2(acc[mt][nt][0] + b0, acc[mt][nt][1] + b1);
                *(float2*)&outp[(size_t)(row + 8) * 1024 + gn] =
                    make_float2(acc[mt][nt][2] + b0, acc[mt][nt][3] + b1);
            }
        }
    }
}

// =============================================================================
// partial KV^T per (b,h): kvT[e][d] = sum_l v[l][e]*k[l][d]
// f16 inputs -> tf32 smem staging -> tf32 register mma (fp32 accumulate)
// =============================================================================
#define SW(r, c) (((r) << 5) + ((c) ^ (((((r) + ((r) >> 3)) & 7)) << 2)))

__global__ void __launch_bounds__(256) kv_partial()
{
    const int bh = blockIdx.x, part = blockIdx.y;
    const int b = bh >> 4, h = bh & 15;

    __shared__ uint32_t vTs[64 * 32];
    __shared__ uint32_t kTs[64 * 32];

    const int tid  = threadIdx.x;
    const int lane = tid & 31;
    const int warp = tid >> 5;
    const int wm = (warp >> 1) * 16;
    const int wn = (warp & 1) * 32;

    float acc[4][4];
#pragma unroll
    for (int i = 0; i < 4; ++i)
#pragma unroll
        for (int t = 0; t < 4; ++t) acc[i][t] = 0.f;

    const int l_lo = tid >> 3;
    const int d8   = (tid & 7) * 8;
    const size_t colbase = (size_t)h * 64;

    for (int l0 = part * LPART; l0 < part * LPART + LPART; l0 += 32) {
        size_t g = ((size_t)(l0 + l_lo) * BB + b) * DD + colbase + d8;
        uint4 rv = *(const uint4*)(g_vh + g);     // 8 halves
        uint4 rk = *(const uint4*)(g_kh + g);
        const __half2* hv = (const __half2*)&rv;
        const __half2* hk = (const __half2*)&rk;
#pragma unroll
        for (int j = 0; j < 4; ++j) {
            float2 fv = __half22float2(hv[j]);
            float2 fk = __half22float2(hk[j]);
            vTs[SW(d8 + 2*j,     l_lo)] = f2tf(fv.x);
            vTs[SW(d8 + 2*j + 1, l_lo)] = f2tf(fv.y);
            kTs[SW(d8 + 2*j,     l_lo)] = f2tf(fk.x);
            kTs[SW(d8 + 2*j + 1, l_lo)] = f2tf(fk.y);
        }
        __syncthreads();

#pragma unroll
        for (int kk = 0; kk < 32; kk += 8) {
            uint32_t af[4];
            int r = wm + (lane >> 2);
            int c = kk + (lane & 3);
            af[0] = vTs[SW(r,     c)];
            af[1] = vTs[SW(r + 8, c)];
            af[2] = vTs[SW(r,     c + 4)];
            af[3] = vTs[SW(r + 8, c + 4)];
#pragma unroll
            for (int nt = 0; nt < 4; ++nt) {
                int rn = wn + nt*8 + (lane >> 2);
                uint32_t b0 = kTs[SW(rn, c)];
                uint32_t b1 = kTs[SW(rn, c + 4)];
                mma8(acc[nt], af, b0, b1);
            }
        }
        __syncthreads();
    }

    float* out = g_kvp + ((size_t)part * BH + bh) * 4096;
#pragma unroll
    for (int nt = 0; nt < 4; ++nt) {
        int e = wm + (lane >> 2);
        int d = wn + nt*8 + 2*(lane & 3);
        *(float2*)&out[(e    ) * 64 + d] = make_float2(acc[nt][0], acc[nt][1]);
        *(float2*)&out[(e + 8) * 64 + d] = make_float2(acc[nt][2], acc[nt][3]);
    }
}

__global__ void kv_reduce() {
    const int bh = blockIdx.x;
    const int tid = threadIdx.x;
#pragma unroll
    for (int j = 0; j < 16; ++j) {
        int i = tid + 256 * j;
        float s = 0.f;
#pragma unroll
        for (int p = 0; p < KV_PARTS; ++p)
            s += g_kvp[((size_t)p * BH + bh) * 4096 + i];
        g_kvT[(size_t)bh * 4096 + i] = s;
    }
}

// =============================================================================
// attn = (q @ kvT^T) * (0.125/scalar) per (b,h); f16 in (q), f16 out
// =============================================================================
__global__ void __launch_bounds__(128) attn_qkv(const float* __restrict__ scalar_ptr)
{
    const int lc = blockIdx.x;
    const int h  = blockIdx.y;
    const int b  = blockIdx.z;
    const int bh = b * 16 + h;
    const int l0 = lc * 64;

    __shared__ uint32_t qs [64][68];
    __shared__ uint32_t kvs[64][68];

    const int tid  = threadIdx.x;
    const int lane = tid & 31;
    const int warp = tid >> 5;
    const int wm   = warp * 16;

#pragma unroll
    for (int i = 0; i < 8; ++i) {
        int s   = tid + 128 * i;
        int row = s >> 4;
        int c4  = (s & 15) * 4;
        uint2 rq = *(const uint2*)(g_qh + ((size_t)(l0 + row) * BB + b) * DD
                                        + (size_t)h * 64 + c4);   // 4 halves
        const __half2* hq = (const __half2*)&rq;
        float2 q0 = __half22float2(hq[0]);
        float2 q1 = __half22float2(hq[1]);
        float4 fk = *(const float4*)(g_kvT + (size_t)bh * 4096 + row * 64 + c4);
        uint4 tq = { f2tf(q0.x), f2tf(q0.y), f2tf(q1.x), f2tf(q1.y) };
        uint4 tk = { f2tf(fk.x), f2tf(fk.y), f2tf(fk.z), f2tf(fk.w) };
        *(uint4*)&qs [row][c4] = tq;
        *(uint4*)&kvs[row][c4] = tk;
    }
    __syncthreads();

    float acc[8][4];
#pragma unroll
    for (int i = 0; i < 8; ++i)
#pragma unroll
        for (int t = 0; t < 4; ++t) acc[i][t] = 0.f;

#pragma unroll
    for (int kk = 0; kk < 64; kk += 8) {
        uint32_t af[4];
        int r = wm + (lane >> 2);
        int c = kk + (lane & 3);
        af[0] = qs[r    ][c    ];
        af[1] = qs[r + 8][c    ];
        af[2] = qs[r    ][c + 4];
        af[3] = qs[r + 8][c + 4];
#pragma unroll
        for (int nt = 0; nt < 8; ++nt) {
            int rn = nt*8 + (lane >> 2);
            uint32_t b0 = kvs[rn][c];
            uint32_t b1 = kvs[rn][c + 4];
            mma8(acc[nt], af, b0, b1);
        }
    }

    const float scale = 0.125f / (*scalar_ptr);
#pragma unroll
    for (int nt = 0; nt < 8; ++nt) {
        int l = l0 + wm + (lane >> 2);
        int e = nt*8 + 2*(lane & 3);
        size_t o0 = ((size_t)l * BB + b) * DD + (size_t)h * 64 + e;
        size_t o1 = ((size_t)(l + 8) * BB + b) * DD + (size_t)h * 64 + e;
        *(__half2*)&g_ah[o0] = __floats2half2_rn(acc[nt][0]*scale, acc[nt][1]*scale);
        *(__half2*)&g_ah[o1] = __floats2half2_rn(acc[nt][2]*scale, acc[nt][3]*scale);
    }
}

// =============================================================================
// launch  (wo_permute_h moved late so gemm_h lands in the profiled launch slot)
// =============================================================================
extern "C" void kernel_launch(void* const* d_in, const int* in_sizes, int n_in,
                              void* d_out, int out_size) {
    const float* x      = (const float*)d_in[0];
    const float* Wq     = (const float*)d_in[2];
    const float* bq     = (const float*)d_in[3];
    const float* Wk     = (const float*)d_in[4];
    const float* bk     = (const float*)d_in[5];
    const float* Wv     = (const float*)d_in[6];
    const float* bv     = (const float*)d_in[7];
    const float* Wo     = (const float*)d_in[8];
    const float* bo     = (const float*)d_in[9];
    const float* scalar = (const float*)d_in[10];
    float* out = (float*)d_out;

    __half *xh, *wh, *woph, *ah, *qh, *kh, *vh;
    float *bqkv;
    cudaGetSymbolAddress((void**)&xh,   g_xh);
    cudaGetSymbolAddress((void**)&wh,   g_wh);
    cudaGetSymbolAddress((void**)&woph, g_woph);
    cudaGetSymbolAddress((void**)&ah,   g_ah);
    cudaGetSymbolAddress((void**)&qh,   g_qh);
    cudaGetSymbolAddress((void**)&kh,   g_kh);
    cudaGetSymbolAddress((void**)&vh,   g_vh);
    cudaGetSymbolAddress((void**)&bqkv, g_bqkv);

    cudaFuncSetAttribute(gemm_h, cudaFuncAttributeMaxDynamicSharedMemorySize, GSMEM);

    // prep: convert/pack to f16
    x_to_h<<<(ROWS*DD)/(256*4), 256>>>(x);
    pack_wh<<<3*DD, 256>>>(Wq, Wk, Wv);
    pack_b<<<3, DD>>>(bq, bk, bv);

    // fused QKV projection: N = 3072, f16 outputs  (profiled slot)
    gemm_h<<<dim3(3*DD/128, ROWS/128), 128, GSMEM>>>(
        xh, wh, bqkv, qh, kh, vh, 1);

    kv_partial<<<dim3(BH, KV_PARTS), 256>>>();
    kv_reduce<<<BH, 256>>>();
    attn_qkv<<<dim3(LL / 64, HH, BB), 128>>>(scalar);

    wo_permute_h<<<DD, 256>>>(Wo);

    // output projection: N = 1024, fp32 output
    gemm_h<<<dim3(DD/128, ROWS/128), 128, GSMEM>>>(
        ah, woph, bo, out, out, out, 0);
}

// round 8
// speedup vs baseline: 1.0276x; 1.0276x over previous
#include <cuda_runtime.h>
#include <cuda_fp16.h>
#include <stdint.h>

// ---------------- problem constants -----------------------------------------
#define LL 4096
#define BB 4
#define DD 1024
#define HH 16
#define HD 64
#define ROWS (LL*BB)          // 16384
#define BH   (BB*HH)          // 64
#define KV_PARTS 16
#define LPART (LL/KV_PARTS)   // 256

// ---------------- scratch (device globals; cudaMalloc is banned) ------------
__device__ __align__(256) __half g_xh  [(size_t)ROWS*DD];    // X in f16
__device__ __align__(256) __half g_wh  [(size_t)3*DD*DD];    // [Wq;Wk;Wv] f16
__device__ __align__(256) __half g_woph[(size_t)DD*DD];      // Wo permuted f16
__device__ __align__(256) float  g_bqkv[(size_t)3*DD];       // [bq;bk;bv]
__device__ __align__(256) __half g_qh  [(size_t)ROWS*DD];    // q (unscaled) f16
__device__ __align__(256) __half g_kh  [(size_t)ROWS*DD];
__device__ __align__(256) __half g_vh  [(size_t)ROWS*DD];
__device__ __align__(256) __half g_ah  [(size_t)ROWS*DD];    // attn out f16
__device__ __align__(256) float  g_kvp [(size_t)KV_PARTS*BH*HD*HD];
__device__ __align__(256) float  g_kvT [(size_t)BH*HD*HD];

// ---------------- helpers -----------------------------------------------------
__device__ __forceinline__ uint32_t f2tf(float x) {
    uint32_t u; asm("cvt.rna.tf32.f32 %0, %1;" : "=r"(u) : "f"(x)); return u;
}
__device__ __forceinline__ uint32_t smem_u32(const void* p) {
    uint32_t a;
    asm("{ .reg .u64 t; cvta.to.shared.u64 t, %1; cvt.u32.u64 %0, t; }" : "=r"(a) : "l"(p));
    return a;
}
__device__ __forceinline__ void cp16(uint32_t saddr, const void* gaddr) {
    asm volatile("cp.async.cg.shared.global [%0], [%1], 16;" :: "r"(saddr), "l"(gaddr));
}
__device__ __forceinline__ void ldsm4(uint32_t* r, uint32_t a) {
    asm volatile("ldmatrix.sync.aligned.m8n8.x4.shared.b16 {%0,%1,%2,%3}, [%4];"
        : "=r"(r[0]), "=r"(r[1]), "=r"(r[2]), "=r"(r[3]) : "r"(a));
}
__device__ __forceinline__ void mma16(float c[4], const uint32_t a[4],
                                      uint32_t b0, uint32_t b1) {
    asm volatile(
        "mma.sync.aligned.m16n8k16.row.col.f32.f16.f16.f32 "
        "{%0,%1,%2,%3}, {%4,%5,%6,%7}, {%8,%9}, {%0,%1,%2,%3};"
        : "+f"(c[0]), "+f"(c[1]), "+f"(c[2]), "+f"(c[3])
        : "r"(a[0]), "r"(a[1]), "r"(a[2]), "r"(a[3]), "r"(b0), "r"(b1));
}
__device__ __forceinline__ void mma8(float c[4], const uint32_t a[4],
                                     uint32_t b0, uint32_t b1) {
    asm volatile(
        "mma.sync.aligned.m16n8k8.row.col.f32.tf32.tf32.f32 "
        "{%0,%1,%2,%3}, {%4,%5,%6,%7}, {%8,%9}, {%0,%1,%2,%3};"
        : "+f"(c[0]), "+f"(c[1]), "+f"(c[2]), "+f"(c[3])
        : "r"(a[0]), "r"(a[1]), "r"(a[2]), "r"(a[3]), "r"(b0), "r"(b1));
}

// =============================================================================
// Prep kernels
// =============================================================================
__global__ void x_to_h(const float* __restrict__ X) {
    size_t i = ((size_t)blockIdx.x * 256 + threadIdx.x) * 4;
    float4 v = *(const float4*)(X + i);
    *(__half2*)(g_xh + i)     = __floats2half2_rn(v.x, v.y);
    *(__half2*)(g_xh + i + 2) = __floats2half2_rn(v.z, v.w);
}

__global__ void pack_wh(const float* __restrict__ Wq, const float* __restrict__ Wk,
                        const float* __restrict__ Wv) {
    int r = blockIdx.x;                                 // 0..3071
    const float* src = (r < 1024) ? Wq : (r < 2048) ? Wk : Wv;
    int lr = r & 1023;
    int c = threadIdx.x * 4;
    float4 v = *(const float4*)(src + (size_t)lr * DD + c);
    *(__half2*)(g_wh + (size_t)r * DD + c)     = __floats2half2_rn(v.x, v.y);
    *(__half2*)(g_wh + (size_t)r * DD + c + 2) = __floats2half2_rn(v.z, v.w);
}

__global__ void pack_b(const float* __restrict__ bq, const float* __restrict__ bk,
                       const float* __restrict__ bv) {
    int t = blockIdx.x;
    const float* src = (t == 0) ? bq : (t == 1) ? bk : bv;
    g_bqkv[t * DD + threadIdx.x] = src[threadIdx.x];
}

// g_woph[j][h*64+t] = half(Wo[j][t*16+h])
__global__ void wo_permute_h(const float* __restrict__ Wo) {
    __shared__ float srow[DD];
    const int j = blockIdx.x, tid = threadIdx.x;
#pragma unroll
    for (int i = 0; i < 4; ++i) srow[tid + 256*i] = Wo[(size_t)j*DD + tid + 256*i];
    __syncthreads();
#pragma unroll
    for (int i = 0; i < 4; ++i) {
        int f = tid + 256*i;
        g_woph[(size_t)j*DD + f] = __float2half_rn(srow[((f & 63) << 4) | (f >> 6)]);
    }
}

// =============================================================================
// FP16 tensor-core GEMM:  C = A @ B^T + bias
//   block 128x128, BK=64, 4 warps, warp tile 64x64, 3-stage cp.async pipeline,
//   ldmatrix.x4, XOR-8 swizzled 128B smem rows, single-buffered fragments
//   (ptxas schedules the latency), single barrier per K-chunk.  2 CTAs/SM.
// =============================================================================
#define STA  16384                 // A stage bytes (128 rows x 128B)
#define STS_ (2*STA)               // 32768
#define GSMEM (3 * STS_)           // 98304
#define NKT  16                    // 1024 / 64

__global__ void __launch_bounds__(128, 2) gemm_h(
    const __half* __restrict__ A, const __half* __restrict__ B,
    const float* __restrict__ bias,
    void* __restrict__ o0, void* __restrict__ o1, void* __restrict__ o2,
    int half_out)
{
    extern __shared__ char smem[];
    const uint32_t sb = smem_u32(smem);
    const int tid  = threadIdx.x;
    const int wid  = tid >> 5;
    const int lane = tid & 31;
    const int n0 = blockIdx.x * 128;
    const int m0 = blockIdx.y * 128;
    const int wm = (wid & 1) * 64;
    const int wn = (wid >> 1) * 64;

    // staging offsets (128B rows, seg ^= row&7 swizzle); same map for A and B
    uint32_t sm_off[8], g_off[8];
#pragma unroll
    for (int i = 0; i < 8; ++i) {
        int s = tid + 128*i, row = s >> 3, seg = s & 7;
        sm_off[i] = row*128 + ((seg ^ (row & 7)) << 4);
        g_off[i]  = (uint32_t)row*2048 + seg*16;
    }
    const char* Abase = (const char*)A + (size_t)m0 * 2048;
    const char* Bbase = (const char*)B + (size_t)n0 * 2048;

#define LOADC(c) do {                                                   \
        int st_ = (c) % 3;                                              \
        uint32_t ab_ = sb + st_*STS_;                                   \
        uint32_t bb_ = ab_ + STA;                                       \
        const char* ga_ = Abase + (size_t)(c)*128;                      \
        const char* gb_ = Bbase + (size_t)(c)*128;                      \
        _Pragma("unroll") for (int i_ = 0; i_ < 8; ++i_) {              \
            cp16(ab_ + sm_off[i_], ga_ + g_off[i_]);                    \
            cp16(bb_ + sm_off[i_], gb_ + g_off[i_]);                    \
        }                                                               \
        asm volatile("cp.async.commit_group;" ::: "memory");            \
    } while (0)

    float acc[4][8][4];
#pragma unroll
    for (int i = 0; i < 4; ++i)
#pragma unroll
        for (int j = 0; j < 8; ++j)
#pragma unroll
            for (int t = 0; t < 4; ++t) acc[i][j][t] = 0.f;

    LOADC(0);
    LOADC(1);

    for (int kt = 0; kt < NKT; ++kt) {
        if (kt + 1 < NKT) asm volatile("cp.async.wait_group 1;" ::: "memory");
        else              asm volatile("cp.async.wait_group 0;" ::: "memory");
        __syncthreads();          // single barrier per K-chunk (3-stage proof)
        if (kt + 2 < NKT) LOADC(kt + 2);

        const uint32_t sa  = sb + (kt % 3) * STS_;
        const uint32_t sbB = sa + STA;

#pragma unroll
        for (int s = 0; s < 4; ++s) {          // four k16 steps within BK=64
            uint32_t af[4][4], bf[4][4];
#pragma unroll
            for (int mt = 0; mt < 4; ++mt) {
                int r  = wm + mt*16 + (lane & 15);
                int sg = (2*s + (lane >> 4)) ^ (r & 7);
                ldsm4(af[mt], sa + r*128 + (sg << 4));
            }
#pragma unroll
            for (int p = 0; p < 4; ++p) {
                int r  = wn + p*16 + (lane & 7) + ((lane >> 4) << 3);
                int sg = (2*s + ((lane >> 3) & 1)) ^ (r & 7);
                ldsm4(bf[p], sbB + r*128 + (sg << 4));
            }
#pragma unroll
            for (int mt = 0; mt < 4; ++mt)
#pragma unroll
                for (int nt = 0; nt < 8; ++nt)
                    mma16(acc[mt][nt], af[mt],
                          bf[nt >> 1][(nt & 1) * 2], bf[nt >> 1][(nt & 1) * 2 + 1]);
        }
    }

    // epilogue
    if (half_out) {
        const int t = n0 >> 10;
        __half* outp = (t == 0) ? (__half*)o0 : (t == 1) ? (__half*)o1 : (__half*)o2;
#pragma unroll
        for (int mt = 0; mt < 4; ++mt) {
#pragma unroll
            for (int nt = 0; nt < 8; ++nt) {
                int row = m0 + wm + mt*16 + (lane >> 2);
                int gn  = n0 + wn + nt*8 + 2*(lane & 3);
                int col = gn & 1023;
                float b0 = bias[gn], b1 = bias[gn + 1];
                *(__half2*)&outp[(size_t)row * 1024 + col] =
                    __floats2half2_rn(acc[mt][nt][0] + b0, acc[mt][nt][1] + b1);
                *(__half2*)&outp[(size_t)(row + 8) * 1024 + col] =
                    __floats2half2_rn(acc[mt][nt][2] + b0, acc[mt][nt][3] + b1);
            }
        }
    } else {
        float* outp = (float*)o0;
#pragma unroll
        for (int mt = 0; mt < 4; ++mt) {
#pragma unroll
            for (int nt = 0; nt < 8; ++nt) {
                int row = m0 + wm + mt*16 + (lane >> 2);
                int gn  = n0 + wn + nt*8 + 2*(lane & 3);
                float b0 = bias[gn], b1 = bias[gn + 1];
                *(float2*)&outp[(size_t)row * 1024 + gn] =
                    make_float2(acc[mt][nt][0] + b0, acc[mt][nt][1] + b1);
                *(float2*)&outp[(size_t)(row + 8) * 1024 + gn] =
                    make_float2(acc[mt][nt][2] + b0, acc[mt][nt][3] + b1);
            }
        }
    }
}

// =============================================================================
// partial KV^T per (b,h): kvT[e][d] = sum_l v[l][e]*k[l][d]
// f16 inputs -> tf32 smem staging -> tf32 register mma (fp32 accumulate)
// =============================================================================
#define SW(r, c) (((r) << 5) + ((c) ^ (((((r) + ((r) >> 3)) & 7)) << 2)))

__global__ void __launch_bounds__(256) kv_partial()
{
    const int bh = blockIdx.x, part = blockIdx.y;
    const int b = bh >> 4, h = bh & 15;

    __shared__ uint32_t vTs[64 * 32];
    __shared__ uint32_t kTs[64 * 32];

    const int tid  = threadIdx.x;
    const int lane = tid & 31;
    const int warp = tid >> 5;
    const int wm = (warp >> 1) * 16;
    const int wn = (warp & 1) * 32;

    float acc[4][4];
#pragma unroll
    for (int i = 0; i < 4; ++i)
#pragma unroll
        for (int t = 0; t < 4; ++t) acc[i][t] = 0.f;

    const int l_lo = tid >> 3;
    const int d8   = (tid & 7) * 8;
    const size_t colbase = (size_t)h * 64;

    for (int l0 = part * LPART; l0 < part * LPART + LPART; l0 += 32) {
        size_t g = ((size_t)(l0 + l_lo) * BB + b) * DD + colbase + d8;
        uint4 rv = *(const uint4*)(g_vh + g);     // 8 halves
        uint4 rk = *(const uint4*)(g_kh + g);
        const __half2* hv = (const __half2*)&rv;
        const __half2* hk = (const __half2*)&rk;
#pragma unroll
        for (int j = 0; j < 4; ++j) {
            float2 fv = __half22float2(hv[j]);
            float2 fk = __half22float2(hk[j]);
            vTs[SW(d8 + 2*j,     l_lo)] = f2tf(fv.x);
            vTs[SW(d8 + 2*j + 1, l_lo)] = f2tf(fv.y);
            kTs[SW(d8 + 2*j,     l_lo)] = f2tf(fk.x);
            kTs[SW(d8 + 2*j + 1, l_lo)] = f2tf(fk.y);
        }
        __syncthreads();

#pragma unroll
        for (int kk = 0; kk < 32; kk += 8) {
            uint32_t af[4];
            int r = wm + (lane >> 2);
            int c = kk + (lane & 3);
            af[0] = vTs[SW(r,     c)];
            af[1] = vTs[SW(r + 8, c)];
            af[2] = vTs[SW(r,     c + 4)];
            af[3] = vTs[SW(r + 8, c + 4)];
#pragma unroll
            for (int nt = 0; nt < 4; ++nt) {
                int rn = wn + nt*8 + (lane >> 2);
                uint32_t b0 = kTs[SW(rn, c)];
                uint32_t b1 = kTs[SW(rn, c + 4)];
                mma8(acc[nt], af, b0, b1);
            }
        }
        __syncthreads();
    }

    float* out = g_kvp + ((size_t)part * BH + bh) * 4096;
#pragma unroll
    for (int nt = 0; nt < 4; ++nt) {
        int e = wm + (lane >> 2);
        int d = wn + nt*8 + 2*(lane & 3);
        *(float2*)&out[(e    ) * 64 + d] = make_float2(acc[nt][0], acc[nt][1]);
        *(float2*)&out[(e + 8) * 64 + d] = make_float2(acc[nt][2], acc[nt][3]);
    }
}

__global__ void kv_reduce() {
    const int bh = blockIdx.x;
    const int tid = threadIdx.x;
#pragma unroll
    for (int j = 0; j < 16; ++j) {
        int i = tid + 256 * j;
        float s = 0.f;
#pragma unroll
        for (int p = 0; p < KV_PARTS; ++p)
            s += g_kvp[((size_t)p * BH + bh) * 4096 + i];
        g_kvT[(size_t)bh * 4096 + i] = s;
    }
}

// =============================================================================
// attn = (q @ kvT^T) * (0.125/scalar) per (b,h); f16 in (q), f16 out
// =============================================================================
__global__ void __launch_bounds__(128) attn_qkv(const float* __restrict__ scalar_ptr)
{
    const int lc = blockIdx.x;
    const int h  = blockIdx.y;
    const int b  = blockIdx.z;
    const int bh = b * 16 + h;
    const int l0 = lc * 64;

    __shared__ uint32_t qs [64][68];
    __shared__ uint32_t kvs[64][68];

    const int tid  = threadIdx.x;
    const int lane = tid & 31;
    const int warp = tid >> 5;
    const int wm   = warp * 16;

#pragma unroll
    for (int i = 0; i < 8; ++i) {
        int s   = tid + 128 * i;
        int row = s >> 4;
        int c4  = (s & 15) * 4;
        uint2 rq = *(const uint2*)(g_qh + ((size_t)(l0 + row) * BB + b) * DD
                                        + (size_t)h * 64 + c4);   // 4 halves
        const __half2* hq = (const __half2*)&rq;
        float2 q0 = __half22float2(hq[0]);
        float2 q1 = __half22float2(hq[1]);
        float4 fk = *(const float4*)(g_kvT + (size_t)bh * 4096 + row * 64 + c4);
        uint4 tq = { f2tf(q0.x), f2tf(q0.y), f2tf(q1.x), f2tf(q1.y) };
        uint4 tk = { f2tf(fk.x), f2tf(fk.y), f2tf(fk.z), f2tf(fk.w) };
        *(uint4*)&qs [row][c4] = tq;
        *(uint4*)&kvs[row][c4] = tk;
    }
    __syncthreads();

    float acc[8][4];
#pragma unroll
    for (int i = 0; i < 8; ++i)
#pragma unroll
        for (int t = 0; t < 4; ++t) acc[i][t] = 0.f;

#pragma unroll
    for (int kk = 0; kk < 64; kk += 8) {
        uint32_t af[4];
        int r = wm + (lane >> 2);
        int c = kk + (lane & 3);
        af[0] = qs[r    ][c    ];
        af[1] = qs[r + 8][c    ];
        af[2] = qs[r    ][c + 4];
        af[3] = qs[r + 8][c + 4];
#pragma unroll
        for (int nt = 0; nt < 8; ++nt) {
            int rn = nt*8 + (lane >> 2);
            uint32_t b0 = kvs[rn][c];
            uint32_t b1 = kvs[rn][c + 4];
            mma8(acc[nt], af, b0, b1);
        }
    }

    const float scale = 0.125f / (*scalar_ptr);
#pragma unroll
    for (int nt = 0; nt < 8; ++nt) {
        int l = l0 + wm + (lane >> 2);
        int e = nt*8 + 2*(lane & 3);
        size_t o0 = ((size_t)l * BB + b) * DD + (size_t)h * 64 + e;
        size_t o1 = ((size_t)(l + 8) * BB + b) * DD + (size_t)h * 64 + e;
        *(__half2*)&g_ah[o0] = __floats2half2_rn(acc[nt][0]*scale, acc[nt][1]*scale);
        *(__half2*)&g_ah[o1] = __floats2half2_rn(acc[nt][2]*scale, acc[nt][3]*scale);
    }
}

// =============================================================================
// launch
// =============================================================================
extern "C" void kernel_launch(void* const* d_in, const int* in_sizes, int n_in,
                              void* d_out, int out_size) {
    const float* x      = (const float*)d_in[0];
    const float* Wq     = (const float*)d_in[2];
    const float* bq     = (const float*)d_in[3];
    const float* Wk     = (const float*)d_in[4];
    const float* bk     = (const float*)d_in[5];
    const float* Wv     = (const float*)d_in[6];
    const float* bv     = (const float*)d_in[7];
    const float* Wo     = (const float*)d_in[8];
    const float* bo     = (const float*)d_in[9];
    const float* scalar = (const float*)d_in[10];
    float* out = (float*)d_out;

    __half *xh, *wh, *woph, *ah, *qh, *kh, *vh;
    float *bqkv;
    cudaGetSymbolAddress((void**)&xh,   g_xh);
    cudaGetSymbolAddress((void**)&wh,   g_wh);
    cudaGetSymbolAddress((void**)&woph, g_woph);
    cudaGetSymbolAddress((void**)&ah,   g_ah);
    cudaGetSymbolAddress((void**)&qh,   g_qh);
    cudaGetSymbolAddress((void**)&kh,   g_kh);
    cudaGetSymbolAddress((void**)&vh,   g_vh);
    cudaGetSymbolAddress((void**)&bqkv, g_bqkv);

    cudaFuncSetAttribute(gemm_h, cudaFuncAttributeMaxDynamicSharedMemorySize, GSMEM);

    // prep: convert/pack to f16
    x_to_h<<<(ROWS*DD)/(256*4), 256>>>(x);
    pack_wh<<<3*DD, 256>>>(Wq, Wk, Wv);
    pack_b<<<3, DD>>>(bq, bk, bv);

    // fused QKV projection: N = 3072, f16 outputs  (profiled slot)
    gemm_h<<<dim3(3*DD/128, ROWS/128), 128, GSMEM>>>(
        xh, wh, bqkv, qh, kh, vh, 1);

    kv_partial<<<dim3(BH, KV_PARTS), 256>>>();
    kv_reduce<<<BH, 256>>>();
    attn_qkv<<<dim3(LL / 64, HH, BB), 128>>>(scalar);

    wo_permute_h<<<DD, 256>>>(Wo);

    // output projection: N = 1024, fp32 output
    gemm_h<<<dim3(DD/128, ROWS/128), 128, GSMEM>>>(
        ah, woph, bo, out, out, out, 0);
}